// round 14
// baseline (speedup 1.0000x reference)
#include <cuda_runtime.h>

#define B_   64
#define D_   25000
#define K_   16
#define H_   128
#define E_   256
#define Z_   32
#define TD   32
#define THR  256
#define NCTA ((D_ + TD - 1) / TD)   /* 782 */

// line-spread pooled accumulator: element i lives at g_c[i*32] (own 128B line)
__device__ float g_c[1024 * 32];
__device__ int   g_cnt;

// ---------------- f32x2 helpers ----------------
__device__ __forceinline__ unsigned long long pk2(float lo, float hi) {
    unsigned long long r;
    asm("mov.b64 %0, {%1, %2};" : "=l"(r) : "f"(lo), "f"(hi));
    return r;
}
__device__ __forceinline__ void fma2(unsigned long long& d,
                                     unsigned long long a, unsigned long long b) {
    asm("fma.rn.f32x2 %0, %1, %2, %3;" : "=l"(d) : "l"(a), "l"(b), "l"(d));
}
__device__ __forceinline__ float2 unpk(unsigned long long v) {
    float2 r;
    asm("mov.b64 {%0, %1}, %2;" : "=f"(r.x), "=f"(r.y) : "l"(v));
    return r;
}

// conflict-free c accumulation index
#define CWSTR 1104
#define CIDX(b) ((b) * 17 + (((b) >> 5) << 3))

// shared-memory byte offsets (main phase)
#define OFF_GS      0        /* f32[32*132]  16896 */
#define OFF_XS      16896    /* f32[32*65]    8320 */
#define OFF_W2P     25216    /* f32[64*32]    8192 */
#define OFF_W1S     33408    /* f32[18*128]   9216 */
#define OFF_B1S     42624    /* f32[128]       512 */
#define OFF_B2S     43136    /* f32[16]         64 */
#define OFF_FES     43200    /* f32[32*16]    2048 */
#define OFF_FBS     45248    /* f32[32]        128 */
#define OFF_CW      45376    /* f32[8*1104]  35328 */
#define OFF_ROWS    80704    /* u32[64]        256 */
#define OFF_MBITS   80960    /* u64[32]        256 */
#define OFF_BLIST   81216    /* u8[32*32]     1024 */
#define OFF_OVF     82240    /* u16[1024]     2048 */
#define OFF_CNT     84288    /* u8[32]          32 */
#define OFF_OVOFF   84320    /* u16[32]         64 */
#define OFF_NOVF    84384    /* int              4 */
// tail phase (aliases everything above; only last CTA uses)
#define OFF_A1      0        /* f32[64*256]  65536 */
#define OFF_CS      65536    /* f32[1024]     4096 */
#define OFF_WE1     69632    /* f32[16*256]  16384 -> 86016 */
#define SMEM_BYTES  86080

// dual-pair fused layer1(rank-1)+relu+layer2: two d's share all W2/w1 loads
__device__ __forceinline__ void pair2_body(const float* __restrict__ gA,
                                           const float* __restrict__ gB,
                                           const float* __restrict__ w1s,
                                           const float* __restrict__ W2p,
                                           const float* __restrict__ b2s,
                                           float xvA, float xvB,
                                           float* __restrict__ h2A,
                                           float* __restrict__ h2B)
{
    unsigned long long accA[K_], accB[K_];
#pragma unroll
    for (int k = 0; k < K_; k++) { accA[k] = 0ULL; accB[k] = 0ULL; }
#pragma unroll 4
    for (int h = 0; h < H_; h += 4) {
        float4 a4 = *(const float4*)(gA + h);
        float4 c4 = *(const float4*)(gB + h);
        float4 w4 = *(const float4*)(w1s + h);
        float eA0 = fmaxf(fmaf(xvA, w4.x, a4.x), 0.0f);
        float eA1 = fmaxf(fmaf(xvA, w4.y, a4.y), 0.0f);
        float eA2 = fmaxf(fmaf(xvA, w4.z, a4.z), 0.0f);
        float eA3 = fmaxf(fmaf(xvA, w4.w, a4.w), 0.0f);
        float eB0 = fmaxf(fmaf(xvB, w4.x, c4.x), 0.0f);
        float eB1 = fmaxf(fmaf(xvB, w4.y, c4.y), 0.0f);
        float eB2 = fmaxf(fmaf(xvB, w4.z, c4.z), 0.0f);
        float eB3 = fmaxf(fmaf(xvB, w4.w, c4.w), 0.0f);
        unsigned long long aA01 = pk2(eA0, eA1);
        unsigned long long aA23 = pk2(eA2, eA3);
        unsigned long long aB01 = pk2(eB0, eB1);
        unsigned long long aB23 = pk2(eB2, eB3);
        const unsigned long long* q0 = (const unsigned long long*)&W2p[(h >> 1) * 32];
        const unsigned long long* q1 = (const unsigned long long*)&W2p[((h >> 1) + 1) * 32];
#pragma unroll
        for (int k = 0; k < K_; k += 2) {
            ulonglong2 w0 = *(const ulonglong2*)(q0 + k);
            ulonglong2 w1 = *(const ulonglong2*)(q1 + k);
            fma2(accA[k],     aA01, w0.x);
            fma2(accA[k + 1], aA01, w0.y);
            fma2(accA[k],     aA23, w1.x);
            fma2(accA[k + 1], aA23, w1.y);
            fma2(accB[k],     aB01, w0.x);
            fma2(accB[k + 1], aB01, w0.y);
            fma2(accB[k],     aB23, w1.x);
            fma2(accB[k + 1], aB23, w1.y);
        }
    }
#pragma unroll
    for (int k = 0; k < K_; k++) {
        float2 va = unpk(accA[k]);
        float2 vb = unpk(accB[k]);
        h2A[k] = fmaxf(va.x + va.y + b2s[k], 0.0f);
        h2B[k] = fmaxf(vb.x + vb.y + b2s[k], 0.0f);
    }
}

// ---------------- K2: everything fused (one launch) ----------------
__global__ void __launch_bounds__(THR, 2)
k2_main(const float* __restrict__ x, const int* __restrict__ mask,
        const float* __restrict__ fe, const float* __restrict__ fb,
        const float* __restrict__ W1, const float* __restrict__ b1,
        const float* __restrict__ W2, const float* __restrict__ b2,
        const float* __restrict__ We1, const float* __restrict__ be1,
        const float* __restrict__ We2, const float* __restrict__ be2,
        float* __restrict__ out)
{
    extern __shared__ __align__(16) char sm[];
    float* Gs  = (float*)(sm + OFF_GS);
    float* xs  = (float*)(sm + OFF_XS);
    float* W2p = (float*)(sm + OFF_W2P);
    float* W1s = (float*)(sm + OFF_W1S);     // row 0 doubles as w1s
    float* b1s = (float*)(sm + OFF_B1S);
    float* b2s = (float*)(sm + OFF_B2S);
    float* fes = (float*)(sm + OFF_FES);
    float* fbs = (float*)(sm + OFF_FBS);
    float* cw  = (float*)(sm + OFF_CW);
    unsigned*           rows  = (unsigned*)          (sm + OFF_ROWS);
    unsigned long long* mbits = (unsigned long long*)(sm + OFF_MBITS);
    unsigned char*  blist   = (unsigned char*) (sm + OFF_BLIST);
    unsigned short* ovf     = (unsigned short*)(sm + OFF_OVF);
    unsigned char*  cnt_all = (unsigned char*) (sm + OFF_CNT);
    unsigned short* ovoff   = (unsigned short*)(sm + OFF_OVOFF);
    int* novf_s = (int*)(sm + OFF_NOVF);
    __shared__ int lastflag;

    const int tid  = threadIdx.x;
    const int w    = tid >> 5;
    const int lane = tid & 31;
    const int d0   = blockIdx.x * TD;
    const int td   = min(TD, D_ - d0);

    // ---- prologue: weights + per-tile inputs ----
    for (int i = tid; i < 18 * H_; i += THR) W1s[i] = W1[i];
    if (tid < H_) b1s[tid] = b1[tid];
    if (tid < K_) b2s[tid] = b2[tid];
    for (int i = tid; i < H_ * K_; i += THR) {
        int h = i >> 4, k = i & 15;
        W2p[(h >> 1) * 32 + ((k << 1) | (h & 1))] = W2[i];
    }
    for (int i = tid; i < 8 * CWSTR; i += THR) cw[i] = 0.0f;
    for (int i = tid; i < td * K_; i += THR) fes[i] = fe[d0 * K_ + i];
    if (tid < td) fbs[tid] = fb[d0 + tid];
    if (td == TD) {
        for (int i = tid; i < B_ * TD; i += THR) {
            int b = i >> 5, dl = i & 31;
            xs[dl * 65 + b] = x[b * D_ + d0 + dl];
        }
    } else {
        for (int i = tid; i < B_ * td; i += THR) {
            int b = i / td, dl = i - b * td;
            xs[dl * 65 + b] = x[b * D_ + d0 + dl];
        }
    }
    // mask: row-coalesced loads + ballot per b-row
#pragma unroll
    for (int j = 0; j < 8; j++) {
        int b = w * 8 + j;
        int m = (lane < td) ? mask[b * D_ + d0 + lane] : 0;
        unsigned bal = __ballot_sync(0xffffffffu, m != 0);
        if (lane == 0) rows[b] = bal;
    }
    __syncthreads();

    // ---- G tile (all threads) + lists (warp 0) ----
    for (int i = tid; i < td * H_; i += THR) {
        int dl = i >> 7, h = i & 127;
        float acc = b1s[h];
        const float* fr = fes + dl * K_;
#pragma unroll
        for (int j = 0; j < K_; j++) acc = fmaf(fr[j], W1s[(1 + j) * H_ + h], acc);
        acc = fmaf(fbs[dl], W1s[17 * H_ + h], acc);
        Gs[dl * 132 + h] = acc;
    }
    if (w == 0) {
        unsigned long long bits = 0ULL;
        if (lane < td) {
#pragma unroll 8
            for (int b = 0; b < B_; b++)
                bits |= (unsigned long long)((rows[b] >> lane) & 1u) << b;
        }
        mbits[lane] = bits;
        cnt_all[lane] = (unsigned char)__popcll(bits);
        __syncwarp();
        if (lane == 0) {
            int nov = 0;
            for (int dl = 0; dl < TD; dl++) {
                ovoff[dl] = (unsigned short)nov;
                int n = cnt_all[dl];
                nov += (n > 32) ? (n - 32) : 0;
            }
            *novf_s = nov;
        }
        __syncwarp();
        int r = 0, o = ovoff[lane];
        while (bits) {
            int b = __ffsll((long long)bits) - 1;
            bits &= bits - 1;
            if (r < 32) blist[lane * 32 + r] = (unsigned char)b;
            else        ovf[o + r - 32] = (unsigned short)((lane << 8) | b);
            r++;
        }
    }
    __syncthreads();

    // ---- main: 2 dual-d passes per warp ----
    float h2A[K_], h2B[K_];
    float* cwb = cw + w * CWSTR;
#pragma unroll 1
    for (int q = 0; q < 2; q++) {
        const int dlA = w * 4 + q * 2;
        const int dlB = dlA + 1;
        const int nmA = (dlA < td) ? min((int)cnt_all[dlA], 32) : 0;
        const int nmB = (dlB < td) ? min((int)cnt_all[dlB], 32) : 0;
        const bool onA = lane < nmA, onB = lane < nmB;
        const int bA = onA ? (int)blist[dlA * 32 + lane] : 0;
        const int bB = onB ? (int)blist[dlB * 32 + lane] : 0;
        const float xvA = onA ? xs[dlA * 65 + bA] : 0.0f;
        const float xvB = onB ? xs[dlB * 65 + bB] : 0.0f;

        pair2_body(Gs + dlA * 132, Gs + dlB * 132, W1s, W2p, b2s, xvA, xvB, h2A, h2B);

        if (onA) {
            float* cp = cwb + CIDX(bA);
#pragma unroll
            for (int k = 0; k < K_; k++) cp[k] += h2A[k];
        }
        __syncwarp();
        if (onB) {
            float* cp = cwb + CIDX(bB);
#pragma unroll
            for (int k = 0; k < K_; k++) cp[k] += h2B[k];
        }
        __syncwarp();
    }

    // ---- overflow: 2 entries per thread; duplicates -> smem atomics ----
    const int novf = *novf_s;
    const int half = (novf + 1) >> 1;
    for (int p = tid; p < half; p += THR) {
        const int eA = ovf[p];
        const int pb = p + half;
        const bool onB2 = pb < novf;
        const int eB = onB2 ? ovf[pb] : eA;
        const int dlA = eA >> 8, bA = eA & 255;
        const int dlB = eB >> 8, bB = eB & 255;
        pair2_body(Gs + dlA * 132, Gs + dlB * 132, W1s, W2p, b2s,
                   xs[dlA * 65 + bA], xs[dlB * 65 + bB], h2A, h2B);
        float* cpA = cwb + CIDX(bA);
#pragma unroll
        for (int k = 0; k < K_; k++) atomicAdd(cpA + k, h2A[k]);
        if (onB2) {
            float* cpB = cwb + CIDX(bB);
#pragma unroll
            for (int k = 0; k < K_; k++) atomicAdd(cpB + k, h2B[k]);
        }
    }
    __syncthreads();

    // ---- epilogue: reduce 8 warp-buffers -> global REDG (line-spread) ----
    for (int i = tid; i < B_ * K_; i += THR) {
        int b = i >> 4, k = i & 15;
        float s = 0.0f;
#pragma unroll
        for (int ww = 0; ww < 8; ww++) s += cw[ww * CWSTR + CIDX(b) + k];
        atomicAdd(&g_c[i * 32], s);
    }

    // ---- elect last CTA ----
    if (tid == 0) {
        __threadfence();
        int old = atomicAdd(&g_cnt, 1);
        lastflag = (old == NCTA - 1);
        if (lastflag) atomicExch(&g_cnt, 0);     // reset for next replay
    }
    __syncthreads();
    if (!lastflag) return;
    __threadfence();

    // ================= tail: encoder MLP (single CTA) =================
    float* a1s  = (float*)(sm + OFF_A1);
    float* cs   = (float*)(sm + OFF_CS);
    float* We1s = (float*)(sm + OFF_WE1);

    for (int i = tid; i < 1024; i += THR) {
        cs[i] = g_c[i * 32];
        g_c[i * 32] = 0.0f;                      // reset for next replay
    }
    for (int i = tid; i < K_ * E_; i += THR) We1s[i] = We1[i];
    __syncthreads();

    // layer 1: thread t = hidden unit e, loop over b
    {
        const int e = tid;
        const float bias = be1[e];
        for (int b = 0; b < B_; b++) {
            float acc = bias;
            const float* crow = cs + b * K_;
#pragma unroll
            for (int k = 0; k < K_; k++) acc = fmaf(crow[k], We1s[k * E_ + e], acc);
            a1s[b * E_ + e] = fmaxf(acc, 0.0f);
        }
    }
    __syncthreads();

    // layer 2: thread t -> (b = t>>2, j-block q = t&3 of 16 j), f32x2 over j-pairs
    {
        const int b = tid >> 2, q = tid & 3;
        const int j0 = q * 16;
        const float* a1row = a1s + b * E_;
        unsigned long long acc[8];
#pragma unroll
        for (int jp = 0; jp < 8; jp++)
            acc[jp] = pk2(be2[j0 + 2 * jp], be2[j0 + 2 * jp + 1]);
#pragma unroll 4
        for (int e = 0; e < E_; e++) {
            float a = a1row[e];
            unsigned long long aa = pk2(a, a);
            const ulonglong2* wr = (const ulonglong2*)(We2 + e * 64 + j0);
            ulonglong2 wa = wr[0], wb = wr[1];
            fma2(acc[0], aa, wa.x);
            fma2(acc[1], aa, wa.y);
            fma2(acc[2], aa, wb.x);
            fma2(acc[3], aa, wb.y);
            ulonglong2 wc = wr[2], wd = wr[3];
            fma2(acc[4], aa, wc.x);
            fma2(acc[5], aa, wc.y);
            fma2(acc[6], aa, wd.x);
            fma2(acc[7], aa, wd.y);
        }
#pragma unroll
        for (int jp = 0; jp < 8; jp++) {
            float2 v = unpk(acc[jp]);
            int j = j0 + 2 * jp;
            if (j < Z_) {
                out[b * Z_ + j]     = v.x;
                out[b * Z_ + j + 1] = v.y;
            } else {
                out[B_ * Z_ + b * Z_ + (j - Z_)]     = v.x;
                out[B_ * Z_ + b * Z_ + (j - Z_) + 1] = v.y;
            }
        }
    }
}

// ---------------- launch ----------------
extern "C" void kernel_launch(void* const* d_in, const int* in_sizes, int n_in,
                              void* d_out, int out_size) {
    const float* x    = (const float*)d_in[0];
    const int*   mask = (const int*)  d_in[1];
    const float* fe   = (const float*)d_in[2];
    const float* fb   = (const float*)d_in[3];
    const float* W1   = (const float*)d_in[4];
    const float* b1   = (const float*)d_in[5];
    const float* W2   = (const float*)d_in[6];
    const float* b2   = (const float*)d_in[7];
    const float* We1  = (const float*)d_in[8];
    const float* be1  = (const float*)d_in[9];
    const float* We2  = (const float*)d_in[10];
    const float* be2  = (const float*)d_in[11];
    float* out = (float*)d_out;

    cudaFuncSetAttribute(k2_main, cudaFuncAttributeMaxDynamicSharedMemorySize, SMEM_BYTES);
    k2_main<<<NCTA, THR, SMEM_BYTES>>>(x, mask, fe, fb, W1, b1, W2, b2,
                                       We1, be1, We2, be2, out);
}

// round 16
// speedup vs baseline: 1.2129x; 1.2129x over previous
#include <cuda_runtime.h>

#define B_   64
#define D_   25000
#define K_   16
#define H_   128
#define E_   256
#define Z_   32
#define TD   32
#define THR  256
#define NCTA ((D_ + TD - 1) / TD)   /* 782 */
#define NCP  784                    /* padded cta dim */

__device__ float g_cpart[B_ * K_ * NCP];   // transposed partials [b*16+k][cta]

// ---------------- f32x2 helpers ----------------
__device__ __forceinline__ unsigned long long pk2(float lo, float hi) {
    unsigned long long r;
    asm("mov.b64 %0, {%1, %2};" : "=l"(r) : "f"(lo), "f"(hi));
    return r;
}
__device__ __forceinline__ void fma2(unsigned long long& d,
                                     unsigned long long a, unsigned long long b) {
    asm("fma.rn.f32x2 %0, %1, %2, %3;" : "=l"(d) : "l"(a), "l"(b), "l"(d));
}
__device__ __forceinline__ float2 unpk(unsigned long long v) {
    float2 r;
    asm("mov.b64 {%0, %1}, %2;" : "=f"(r.x), "=f"(r.y) : "l"(v));
    return r;
}

// conflict-free c accumulation index
#define CWSTR 1104
#define CIDX(b) ((b) * 17 + (((b) >> 5) << 3))

// shared-memory byte offsets (cw aliases build-phase scratch)
#define OFF_MBITS   0        /* u64[32]            256  */
#define OFF_GS      256      /* f32[32*132]      16896  */
#define OFF_XS      17152    /* f32[32*65]        8320  */
#define OFF_W2P     25472    /* f32[64*32]        8192  */
#define OFF_W1S0    33664    /* f32[128]           512  */
#define OFF_CW      34176    /* f32[8*1104]      35328  */
#define OFF_B2S     69504    /* f32[16]             64  */
#define OFF_BLIST   69568    /* u8[32*32]         1024  */
#define OFF_OVF     70592    /* u16[32*32]        2048  */
#define OFF_CNT     72640    /* u8[32]              32  */
#define OFF_OVOFF   72672    /* u16[32]             64  */
#define OFF_NOVF    72736    /* int                  4  */
#define OFF_ROWS    72740    /* u32[64]            256  */
#define SMEM_BYTES  73000    /* x3 = 219000 <= 228KB/SM */

// single-d fused layer1(rank-1)+relu+layer2, full-k f32x2 accumulation (low-reg)
__device__ __forceinline__ void pair_body(const float* __restrict__ grow,
                                          const float* __restrict__ w1s,
                                          const float* __restrict__ W2p,
                                          const float* __restrict__ b2s,
                                          float xv, float* __restrict__ h2)
{
    unsigned long long acc[K_];
#pragma unroll
    for (int k = 0; k < K_; k++) acc[k] = 0ULL;
#pragma unroll 2
    for (int h = 0; h < H_; h += 4) {
        float4 g4 = *(const float4*)(grow + h);
        float4 w4 = *(const float4*)(w1s + h);
        float e0 = fmaxf(fmaf(xv, w4.x, g4.x), 0.0f);
        float e1 = fmaxf(fmaf(xv, w4.y, g4.y), 0.0f);
        float e2 = fmaxf(fmaf(xv, w4.z, g4.z), 0.0f);
        float e3 = fmaxf(fmaf(xv, w4.w, g4.w), 0.0f);
        unsigned long long a01 = pk2(e0, e1);
        unsigned long long a23 = pk2(e2, e3);
        const unsigned long long* q0 = (const unsigned long long*)&W2p[(h >> 1) * 32];
        const unsigned long long* q1 = q0 + 16;
#pragma unroll
        for (int k = 0; k < K_; k += 2) {
            ulonglong2 w0 = *(const ulonglong2*)(q0 + k);
            ulonglong2 w1 = *(const ulonglong2*)(q1 + k);
            fma2(acc[k],     a01, w0.x);
            fma2(acc[k + 1], a01, w0.y);
            fma2(acc[k],     a23, w1.x);
            fma2(acc[k + 1], a23, w1.y);
        }
    }
#pragma unroll
    for (int k = 0; k < K_; k++) {
        float2 v = unpk(acc[k]);
        h2[k] = fmaxf(v.x + v.y + b2s[k], 0.0f);
    }
}

// ---------------- K2: fused G-precompute + layer1+layer2 + masked pooling ----------------
__global__ void __launch_bounds__(THR, 3)
k2_main(const float* __restrict__ x, const int* __restrict__ mask,
        const float* __restrict__ fe, const float* __restrict__ fb,
        const float* __restrict__ W1, const float* __restrict__ b1,
        const float* __restrict__ W2, const float* __restrict__ b2)
{
    extern __shared__ __align__(16) char sm[];
    unsigned long long* mbits = (unsigned long long*)(sm + OFF_MBITS);
    float* Gs  = (float*)(sm + OFF_GS);
    float* xs  = (float*)(sm + OFF_XS);
    float* W2p = (float*)(sm + OFF_W2P);
    float* w1s = (float*)(sm + OFF_W1S0);
    float* cw  = (float*)(sm + OFF_CW);
    float* b2s = (float*)(sm + OFF_B2S);
    unsigned char*  blist   = (unsigned char*) (sm + OFF_BLIST);
    unsigned short* ovf     = (unsigned short*)(sm + OFF_OVF);
    unsigned char*  cnt_all = (unsigned char*) (sm + OFF_CNT);
    unsigned short* ovoff   = (unsigned short*)(sm + OFF_OVOFF);
    int* novf_s = (int*)(sm + OFF_NOVF);
    unsigned* rows = (unsigned*)(sm + OFF_ROWS);

    // build-phase scratch aliased inside cw (zeroed later)
    float* W1s = cw;            // [18][128]
    float* fes = cw + 2304;     // [TD][16]
    float* fbs = cw + 2816;     // [TD]
    float* b1s = cw + 2848;     // [128]

    const int tid  = threadIdx.x;
    const int d0   = blockIdx.x * TD;
    const int td   = min(TD, D_ - d0);
    const int w    = tid >> 5;
    const int lane = tid & 31;

    // ---- cooperative loads ----
    for (int i = tid; i < 18 * H_; i += THR) W1s[i] = W1[i];
    for (int i = tid; i < td * K_; i += THR) fes[i] = fe[d0 * K_ + i];
    if (tid < td) fbs[tid] = fb[d0 + tid];
    if (tid < H_) { b1s[tid] = b1[tid]; w1s[tid] = W1[tid]; }
    if (tid < K_) b2s[tid] = b2[tid];
    for (int i = tid; i < H_ * K_; i += THR) {
        int h = i >> 4, k = i & 15;
        W2p[(h >> 1) * 32 + ((k << 1) | (h & 1))] = W2[i];
    }
    if (td == TD) {
        for (int i = tid; i < B_ * TD; i += THR) {
            int b = i >> 5, dl = i & 31;
            xs[dl * 65 + b] = x[b * D_ + d0 + dl];
        }
    } else {
        for (int i = tid; i < B_ * td; i += THR) {
            int b = i / td, dl = i - b * td;
            xs[dl * 65 + b] = x[b * D_ + d0 + dl];
        }
    }
    // mask: row-coalesced loads + ballot per b-row
#pragma unroll
    for (int j = 0; j < 8; j++) {
        int b = w * 8 + j;
        int m = (lane < td) ? mask[b * D_ + d0 + lane] : 0;
        unsigned bal = __ballot_sync(0xffffffffu, m != 0);
        if (lane == 0) rows[b] = bal;
    }
    __syncthreads();

    // ---- G tile (all threads, reads cw-aliased W1s) + lists (warp 0) ----
    for (int i = tid; i < td * H_; i += THR) {
        int dl = i >> 7, h = i & 127;
        float acc = b1s[h];
        const float* fr = fes + dl * K_;
#pragma unroll
        for (int j = 0; j < K_; j++) acc = fmaf(fr[j], W1s[(1 + j) * H_ + h], acc);
        acc = fmaf(fbs[dl], W1s[17 * H_ + h], acc);
        Gs[dl * 132 + h] = acc;
    }
    if (w == 0) {
        // bit-transpose rows[64] -> mbits[dl]
        unsigned long long bits = 0ULL;
        if (lane < td) {
#pragma unroll 8
            for (int b = 0; b < B_; b++)
                bits |= (unsigned long long)((rows[b] >> lane) & 1u) << b;
        }
        mbits[lane] = bits;
        cnt_all[lane] = (unsigned char)__popcll(bits);
        __syncwarp();
        if (lane == 0) {
            int nov = 0;
            for (int dl = 0; dl < TD; dl++) {
                ovoff[dl] = (unsigned short)nov;
                int n = cnt_all[dl];
                nov += (n > 32) ? (n - 32) : 0;
            }
            *novf_s = nov;
        }
        __syncwarp();
        // walk own bits: rank<32 -> blist, rank>=32 -> ovf
        int r = 0, o = ovoff[lane];
        while (bits) {
            int b = __ffsll((long long)bits) - 1;
            bits &= bits - 1;
            if (r < 32) blist[lane * 32 + r] = (unsigned char)b;
            else        ovf[o + r - 32] = (unsigned short)((lane << 8) | b);
            r++;
        }
    }
    __syncthreads();

    // ---- zero cw (W1s/fes/fbs/b1s scratch now dead) ----
    for (int i = tid; i < 8 * CWSTR; i += THR) cw[i] = 0.0f;
    __syncthreads();

    // ---- main: 4 single-d passes per warp; lanes = distinct active b → race-free ----
    float h2[K_];
    float* cwb = cw + w * CWSTR;
#pragma unroll 1
    for (int q = 0; q < 4; q++) {
        const int dl = w * 4 + q;
        const int nm = (dl < td) ? min((int)cnt_all[dl], 32) : 0;
        if (lane < nm) {
            const int b = blist[dl * 32 + lane];
            pair_body(Gs + dl * 132, w1s, W2p, b2s, xs[dl * 65 + b], h2);
            float* cp = cwb + CIDX(b);
#pragma unroll
            for (int k = 0; k < K_; k++) cp[k] += h2[k];
        }
        __syncwarp();
    }

    // ---- overflow: cross-d packed; duplicates possible -> smem atomics (low volume) ----
    const int novf = *novf_s;
    for (int p = tid; p < novf; p += THR) {
        const int e = ovf[p];
        const int dl = e >> 8, b = e & 255;
        pair_body(Gs + dl * 132, w1s, W2p, b2s, xs[dl * 65 + b], h2);
        float* cp = cwb + CIDX(b);
#pragma unroll
        for (int k = 0; k < K_; k++) atomicAdd(cp + k, h2[k]);
    }
    __syncthreads();

    // ---- reduce 8 warp-buffers -> transposed per-CTA partial ----
    for (int i = tid; i < B_ * K_; i += THR) {
        int b = i >> 4, k = i & 15;
        float s = 0.0f;
#pragma unroll
        for (int ww = 0; ww < 8; ww++) s += cw[ww * CWSTR + CIDX(b) + k];
        g_cpart[i * NCP + blockIdx.x] = s;
    }
}

// ---------------- K3: coalesced partial-reduce + encoder MLP, one block per b ----------------
__global__ void __launch_bounds__(256)
k3_enc(const float* __restrict__ We1, const float* __restrict__ be1,
       const float* __restrict__ We2, const float* __restrict__ be2,
       float* __restrict__ out)
{
    __shared__ float cfin[K_];
    __shared__ float a1s[E_];
    __shared__ float ps[4 * 65];
    const int b = blockIdx.x, t = threadIdx.x;
    const int w = t >> 5, lane = t & 31;

    // warp w reduces k = 2w, 2w+1 over 782 CTA partials (coalesced)
#pragma unroll
    for (int j = 0; j < 2; j++) {
        int k = w * 2 + j;
        const float* src = g_cpart + (b * K_ + k) * NCP;
        float s = 0.0f;
        for (int c = lane; c < NCTA; c += 32) s += src[c];
#pragma unroll
        for (int o = 16; o; o >>= 1) s += __shfl_xor_sync(0xffffffffu, s, o);
        if (lane == 0) cfin[k] = s;
    }
    __syncthreads();

    // encoder layer 1: thread t -> hidden unit e
    {
        float acc = be1[t];
#pragma unroll
        for (int k = 0; k < K_; k++) acc = fmaf(cfin[k], We1[k * E_ + t], acc);
        a1s[t] = fmaxf(acc, 0.0f);
    }
    __syncthreads();

    // encoder layer 2: 64 j x 4 e-groups, then reduce
    {
        int j = t & 63, g = t >> 6;
        float p = 0.0f;
#pragma unroll 8
        for (int e = g * 64; e < g * 64 + 64; e++)
            p = fmaf(a1s[e], We2[e * 64 + j], p);
        ps[g * 65 + j] = p;
    }
    __syncthreads();
    if (t < 64) {
        float v = be2[t] + ps[t] + ps[65 + t] + ps[130 + t] + ps[195 + t];
        if (t < Z_) out[b * Z_ + t] = v;                      // mu
        else        out[B_ * Z_ + b * Z_ + (t - Z_)] = v;     // logvar
    }
}

// ---------------- launch ----------------
extern "C" void kernel_launch(void* const* d_in, const int* in_sizes, int n_in,
                              void* d_out, int out_size) {
    const float* x    = (const float*)d_in[0];
    const int*   mask = (const int*)  d_in[1];
    const float* fe   = (const float*)d_in[2];
    const float* fb   = (const float*)d_in[3];
    const float* W1   = (const float*)d_in[4];
    const float* b1   = (const float*)d_in[5];
    const float* W2   = (const float*)d_in[6];
    const float* b2   = (const float*)d_in[7];
    const float* We1  = (const float*)d_in[8];
    const float* be1  = (const float*)d_in[9];
    const float* We2  = (const float*)d_in[10];
    const float* be2  = (const float*)d_in[11];
    float* out = (float*)d_out;

    cudaFuncSetAttribute(k2_main, cudaFuncAttributeMaxDynamicSharedMemorySize, SMEM_BYTES);
    k2_main<<<NCTA, THR, SMEM_BYTES>>>(x, mask, fe, fb, W1, b1, W2, b2);
    k3_enc<<<B_, 256>>>(We1, be1, We2, be2, out);
}

// round 17
// speedup vs baseline: 1.3284x; 1.0952x over previous
#include <cuda_runtime.h>

#define B_   64
#define D_   25000
#define K_   16
#define H_   128
#define E_   256
#define Z_   32
#define TD   32
#define THR  256
#define NCTA ((D_ + TD - 1) / TD)   /* 782 */
#define NCP  784                    /* padded cta dim */

__device__ float g_cpart[B_ * K_ * NCP];   // transposed partials [b*16+k][cta]

// ---------------- f32x2 helpers ----------------
__device__ __forceinline__ unsigned long long pk2(float lo, float hi) {
    unsigned long long r;
    asm("mov.b64 %0, {%1, %2};" : "=l"(r) : "f"(lo), "f"(hi));
    return r;
}
__device__ __forceinline__ void fma2(unsigned long long& d,
                                     unsigned long long a, unsigned long long b) {
    asm("fma.rn.f32x2 %0, %1, %2, %3;" : "=l"(d) : "l"(a), "l"(b), "l"(d));
}
__device__ __forceinline__ float2 unpk(unsigned long long v) {
    float2 r;
    asm("mov.b64 {%0, %1}, %2;" : "=f"(r.x), "=f"(r.y) : "l"(v));
    return r;
}

// conflict-free c accumulation index (b and b+32 land in different banks)
#define CWSTR 1104
#define CIDX(b) ((b) * 17 + (((b) >> 5) << 3))

// shared-memory byte offsets
#define OFF_MBITS   0        /* u64[32]            256  */
#define OFF_GS      256      /* f32[32*132]      16896  */
#define OFF_XS      17152    /* f32[32*65]        8320  */
#define OFF_W2P     25472    /* f32[64*32]        8192  */
#define OFF_W1S0    33664    /* f32[128]           512  */
#define OFF_CW      34176    /* f32[8*1104]      35328  */
#define OFF_B2S     69504    /* f32[16]             64  */
#define OFF_BLIST   69568    /* u8[32*32]         1024  */
#define OFF_OVF     70592    /* u16[32*32]        2048  */
#define OFF_CNT     72640    /* u8[32]              32  */
#define OFF_OVOFF   72672    /* u16[32]             64  */
#define OFF_NOVF    72736    /* int                  4  */
#define SMEM_BYTES  72768

// dual-pair fused layer1(rank-1)+relu+layer2: two d's share all W2/w1 loads
__device__ __forceinline__ void pair2_body(const float* __restrict__ gA,
                                           const float* __restrict__ gB,
                                           const float* __restrict__ w1s,
                                           const float* __restrict__ W2p,
                                           const float* __restrict__ b2s,
                                           float xvA, float xvB,
                                           float* __restrict__ h2A,
                                           float* __restrict__ h2B)
{
    unsigned long long accA[K_], accB[K_];
#pragma unroll
    for (int k = 0; k < K_; k++) { accA[k] = 0ULL; accB[k] = 0ULL; }
#pragma unroll 4
    for (int h = 0; h < H_; h += 4) {
        float4 a4 = *(const float4*)(gA + h);
        float4 c4 = *(const float4*)(gB + h);
        float4 w4 = *(const float4*)(w1s + h);
        float eA0 = fmaxf(fmaf(xvA, w4.x, a4.x), 0.0f);
        float eA1 = fmaxf(fmaf(xvA, w4.y, a4.y), 0.0f);
        float eA2 = fmaxf(fmaf(xvA, w4.z, a4.z), 0.0f);
        float eA3 = fmaxf(fmaf(xvA, w4.w, a4.w), 0.0f);
        float eB0 = fmaxf(fmaf(xvB, w4.x, c4.x), 0.0f);
        float eB1 = fmaxf(fmaf(xvB, w4.y, c4.y), 0.0f);
        float eB2 = fmaxf(fmaf(xvB, w4.z, c4.z), 0.0f);
        float eB3 = fmaxf(fmaf(xvB, w4.w, c4.w), 0.0f);
        unsigned long long aA01 = pk2(eA0, eA1);
        unsigned long long aA23 = pk2(eA2, eA3);
        unsigned long long aB01 = pk2(eB0, eB1);
        unsigned long long aB23 = pk2(eB2, eB3);
        const unsigned long long* q0 = (const unsigned long long*)&W2p[(h >> 1) * 32];
        const unsigned long long* q1 = (const unsigned long long*)&W2p[((h >> 1) + 1) * 32];
#pragma unroll
        for (int k = 0; k < K_; k += 2) {
            ulonglong2 w0 = *(const ulonglong2*)(q0 + k);
            ulonglong2 w1 = *(const ulonglong2*)(q1 + k);
            fma2(accA[k],     aA01, w0.x);
            fma2(accA[k + 1], aA01, w0.y);
            fma2(accA[k],     aA23, w1.x);
            fma2(accA[k + 1], aA23, w1.y);
            fma2(accB[k],     aB01, w0.x);
            fma2(accB[k + 1], aB01, w0.y);
            fma2(accB[k],     aB23, w1.x);
            fma2(accB[k + 1], aB23, w1.y);
        }
    }
#pragma unroll
    for (int k = 0; k < K_; k++) {
        float2 va = unpk(accA[k]);
        float2 vb = unpk(accB[k]);
        h2A[k] = fmaxf(va.x + va.y + b2s[k], 0.0f);
        h2B[k] = fmaxf(vb.x + vb.y + b2s[k], 0.0f);
    }
}

// ---------------- K2: fused G-precompute + layer1+layer2 + masked pooling ----------------
__global__ void __launch_bounds__(THR, 2)
k2_main(const float* __restrict__ x, const int* __restrict__ mask,
        const float* __restrict__ fe, const float* __restrict__ fb,
        const float* __restrict__ W1, const float* __restrict__ b1,
        const float* __restrict__ W2, const float* __restrict__ b2)
{
    extern __shared__ __align__(16) char sm[];
    unsigned long long* mbits = (unsigned long long*)(sm + OFF_MBITS);
    float* Gs  = (float*)(sm + OFF_GS);
    float* xs  = (float*)(sm + OFF_XS);
    float* W2p = (float*)(sm + OFF_W2P);
    float* w1s = (float*)(sm + OFF_W1S0);
    float* cw  = (float*)(sm + OFF_CW);
    float* b2s = (float*)(sm + OFF_B2S);
    unsigned char*  blist   = (unsigned char*) (sm + OFF_BLIST);
    unsigned short* ovf     = (unsigned short*)(sm + OFF_OVF);
    unsigned char*  cnt_all = (unsigned char*) (sm + OFF_CNT);
    unsigned short* ovoff   = (unsigned short*)(sm + OFF_OVOFF);
    int* novf_s = (int*)(sm + OFF_NOVF);

    // build-phase scratch aliased inside cw (zeroed later)
    float* W1s = cw;            // [18][128]
    float* fes = cw + 2304;     // [TD][16]
    float* fbs = cw + 2816;     // [TD]
    float* b1s = cw + 2848;     // [128]

    const int tid  = threadIdx.x;
    const int d0   = blockIdx.x * TD;
    const int td   = min(TD, D_ - d0);
    const int w    = tid >> 5;
    const int lane = tid & 31;

    // ---- cooperative loads ----
    for (int i = tid; i < 18 * H_; i += THR) W1s[i] = W1[i];
    for (int i = tid; i < td * K_; i += THR) fes[i] = fe[d0 * K_ + i];
    if (tid < td) fbs[tid] = fb[d0 + tid];
    if (tid < H_) { b1s[tid] = b1[tid]; w1s[tid] = W1[tid]; }
    if (tid < K_) b2s[tid] = b2[tid];
    for (int i = tid; i < H_ * K_; i += THR) {
        int h = i >> 4, k = i & 15;
        W2p[(h >> 1) * 32 + ((k << 1) | (h & 1))] = W2[i];
    }
    for (int i = tid; i < B_ * td; i += THR) {
        int b = i / td, dl = i - b * td;
        xs[dl * 65 + b] = x[b * D_ + d0 + dl];
    }
    __syncthreads();

    // ---- fused k1: G tile in smem ----
    for (int i = tid; i < td * H_; i += THR) {
        int dl = i >> 7, h = i & 127;
        float acc = b1s[h];
        const float* fr = fes + dl * K_;
#pragma unroll
        for (int j = 0; j < K_; j++) acc = fmaf(fr[j], W1s[(1 + j) * H_ + h], acc);
        acc = fmaf(fbs[dl], W1s[17 * H_ + h], acc);
        Gs[dl * 132 + h] = acc;
    }

    // ---- mask ballots + main-list ranks (lanes = b, b+32) ----
#pragma unroll
    for (int q = 0; q < 4; q++) {
        int dl = w * 4 + q;
        int onlo = 0, onhi = 0;
        if (dl < td) {
            onlo = mask[lane * D_ + d0 + dl];
            onhi = mask[(lane + 32) * D_ + d0 + dl];
        }
        unsigned lo = __ballot_sync(0xffffffffu, onlo != 0);
        unsigned hi = __ballot_sync(0xffffffffu, onhi != 0);
        if (dl < td) {
            if (lane == 0) {
                mbits[dl] = ((unsigned long long)hi << 32) | lo;
                cnt_all[dl] = (unsigned char)(__popc(lo) + __popc(hi));
            }
            if (onlo) {
                int r = __popc(lo & ((1u << lane) - 1u));
                if (r < 32) blist[dl * 32 + r] = (unsigned char)lane;
            }
            if (onhi) {
                int r = __popc(lo) + __popc(hi & ((1u << lane) - 1u));
                if (r < 32) blist[dl * 32 + r] = (unsigned char)(32 + lane);
            }
        } else if (lane == 0) {
            mbits[dl] = 0ULL; cnt_all[dl] = 0;
        }
    }
    __syncthreads();

    // ---- overflow offsets (exclusive scan) + zero cw ----
    if (tid == 0) {
        int nov = 0;
        for (int dl = 0; dl < TD; dl++) {
            ovoff[dl] = (unsigned short)nov;
            int n = cnt_all[dl];
            nov += (n > 32) ? (n - 32) : 0;
        }
        *novf_s = nov;
    }
    for (int i = tid; i < 8 * CWSTR; i += THR) cw[i] = 0.0f;
    __syncthreads();

    // ---- fill overflow list (entries with rank >= 32) ----
#pragma unroll
    for (int q = 0; q < 4; q++) {
        int dl = w * 4 + q;
        if (dl < td) {
            unsigned long long bits = mbits[dl];
            unsigned lo = (unsigned)bits, hi = (unsigned)(bits >> 32);
            if ((lo >> lane) & 1u) {
                int r = __popc(lo & ((1u << lane) - 1u));
                if (r >= 32) ovf[ovoff[dl] + r - 32] = (unsigned short)((dl << 8) | lane);
            }
            if ((hi >> lane) & 1u) {
                int r = __popc(lo) + __popc(hi & ((1u << lane) - 1u));
                if (r >= 32) ovf[ovoff[dl] + r - 32] = (unsigned short)((dl << 8) | (32 + lane));
            }
        }
    }
    __syncthreads();

    // ---- main: 2 dual-d passes per warp; lanes = distinct active b → race-free smem RMW ----
    float* cwb = cw + w * CWSTR;
    float h2A[K_], h2B[K_];
#pragma unroll 1
    for (int q = 0; q < 2; q++) {
        const int dlA = w * 4 + q * 2;
        const int dlB = dlA + 1;
        const int nmA = (dlA < td) ? min((int)cnt_all[dlA], 32) : 0;
        const int nmB = (dlB < td) ? min((int)cnt_all[dlB], 32) : 0;
        const bool onA = lane < nmA, onB = lane < nmB;
        const int bA = onA ? (int)blist[dlA * 32 + lane] : 0;
        const int bB = onB ? (int)blist[dlB * 32 + lane] : 0;
        const float xvA = onA ? xs[dlA * 65 + bA] : 0.0f;
        const float xvB = onB ? xs[dlB * 65 + bB] : 0.0f;

        pair2_body(Gs + dlA * 132, Gs + dlB * 132, w1s, W2p, b2s, xvA, xvB, h2A, h2B);

        if (onA) {
            float* cp = cwb + CIDX(bA);
#pragma unroll
            for (int k = 0; k < K_; k++) cp[k] += h2A[k];
        }
        __syncwarp();
        if (onB) {
            float* cp = cwb + CIDX(bB);
#pragma unroll
            for (int k = 0; k < K_; k++) cp[k] += h2B[k];
        }
        __syncwarp();
    }

    // ---- overflow: cross-d packed, 2 entries per thread; duplicates possible → smem atomics ----
    const int novf = *novf_s;
    const int half = (novf + 1) >> 1;
    for (int p = tid; p < half; p += THR) {
        const int eA = ovf[p];
        const int pb = p + half;
        const bool onB = pb < novf;
        const int eB = onB ? ovf[pb] : eA;
        const int dlA = eA >> 8, bA = eA & 255;
        const int dlB = eB >> 8, bB = eB & 255;
        pair2_body(Gs + dlA * 132, Gs + dlB * 132, w1s, W2p, b2s,
                   xs[dlA * 65 + bA], xs[dlB * 65 + bB], h2A, h2B);
        float* cpA = cwb + CIDX(bA);
#pragma unroll
        for (int k = 0; k < K_; k++) atomicAdd(cpA + k, h2A[k]);
        if (onB) {
            float* cpB = cwb + CIDX(bB);
#pragma unroll
            for (int k = 0; k < K_; k++) atomicAdd(cpB + k, h2B[k]);
        }
    }
    __syncthreads();

    // ---- reduce 8 warp-buffers → transposed per-CTA partial ----
    for (int i = tid; i < B_ * K_; i += THR) {
        int b = i >> 4, k = i & 15;
        float s = 0.0f;
#pragma unroll
        for (int ww = 0; ww < 8; ww++) s += cw[ww * CWSTR + CIDX(b) + k];
        g_cpart[i * NCP + blockIdx.x] = s;
    }
}

// ---------------- K3: coalesced partial-reduce + encoder MLP, one block per b ----------------
__global__ void __launch_bounds__(256)
k3_enc(const float* __restrict__ We1, const float* __restrict__ be1,
       const float* __restrict__ We2, const float* __restrict__ be2,
       float* __restrict__ out)
{
    __shared__ float cfin[K_];
    __shared__ float a1s[E_];
    __shared__ float ps[4 * 65];
    const int b = blockIdx.x, t = threadIdx.x;
    const int w = t >> 5, lane = t & 31;

    // warp w reduces k = 2w, 2w+1 over 782 CTA partials (coalesced)
#pragma unroll
    for (int j = 0; j < 2; j++) {
        int k = w * 2 + j;
        const float* src = g_cpart + (b * K_ + k) * NCP;
        float s = 0.0f;
        for (int c = lane; c < NCTA; c += 32) s += src[c];
#pragma unroll
        for (int o = 16; o; o >>= 1) s += __shfl_xor_sync(0xffffffffu, s, o);
        if (lane == 0) cfin[k] = s;
    }
    __syncthreads();

    // encoder layer 1: thread t -> hidden unit e
    {
        float acc = be1[t];
#pragma unroll
        for (int k = 0; k < K_; k++) acc = fmaf(cfin[k], We1[k * E_ + t], acc);
        a1s[t] = fmaxf(acc, 0.0f);
    }
    __syncthreads();

    // encoder layer 2: 64 j x 4 e-groups, then reduce
    {
        int j = t & 63, g = t >> 6;
        float p = 0.0f;
#pragma unroll 8
        for (int e = g * 64; e < g * 64 + 64; e++)
            p = fmaf(a1s[e], We2[e * 64 + j], p);
        ps[g * 65 + j] = p;
    }
    __syncthreads();
    if (t < 64) {
        float v = be2[t] + ps[t] + ps[65 + t] + ps[130 + t] + ps[195 + t];
        if (t < Z_) out[b * Z_ + t] = v;                      // mu
        else        out[B_ * Z_ + b * Z_ + (t - Z_)] = v;     // logvar
    }
}

// ---------------- launch ----------------
extern "C" void kernel_launch(void* const* d_in, const int* in_sizes, int n_in,
                              void* d_out, int out_size) {
    const float* x    = (const float*)d_in[0];
    const int*   mask = (const int*)  d_in[1];
    const float* fe   = (const float*)d_in[2];
    const float* fb   = (const float*)d_in[3];
    const float* W1   = (const float*)d_in[4];
    const float* b1   = (const float*)d_in[5];
    const float* W2   = (const float*)d_in[6];
    const float* b2   = (const float*)d_in[7];
    const float* We1  = (const float*)d_in[8];
    const float* be1  = (const float*)d_in[9];
    const float* We2  = (const float*)d_in[10];
    const float* be2  = (const float*)d_in[11];
    float* out = (float*)d_out;

    cudaFuncSetAttribute(k2_main, cudaFuncAttributeMaxDynamicSharedMemorySize, SMEM_BYTES);
    k2_main<<<NCTA, THR, SMEM_BYTES>>>(x, mask, fe, fb, W1, b1, W2, b2);
    k3_enc<<<B_, 256>>>(We1, be1, We2, be2, out);
}